// round 11
// baseline (speedup 1.0000x reference)
#include <cuda_runtime.h>
#include <math.h>

#define BSZ   2
#define CH    256
#define SCTX  1024
#define NH    8
#define HD    32
#define TTOT  8525

typedef unsigned long long ull;

__device__ __forceinline__ void fma2(ull& d, ull a, ull b) {
    asm("fma.rn.f32x2 %0, %1, %2, %0;" : "+l"(d) : "l"(a), "l"(b));
}
__device__ __forceinline__ void mul2(ull& d, ull a) {
    asm("mul.rn.f32x2 %0, %0, %1;" : "+l"(d) : "l"(a));
}
__device__ __forceinline__ ull bcast2(float f) {
    ull d; unsigned u = __float_as_uint(f);
    asm("mov.b64 %0, {%1, %1};" : "=l"(d) : "r"(u));
    return d;
}
__device__ __forceinline__ ull pack2(float lo, float hi) {
    ull d; unsigned a = __float_as_uint(lo), b = __float_as_uint(hi);
    asm("mov.b64 %0, {%1, %2};" : "=l"(d) : "r"(a), "r"(b));
    return d;
}
__device__ __forceinline__ float2 unpack2(ull v) {
    unsigned lo, hi;
    asm("mov.b64 {%0, %1}, %2;" : "=r"(lo), "=r"(hi) : "l"(v));
    return make_float2(__uint_as_float(lo), __uint_as_float(hi));
}

__device__ float g_v    [BSZ * TTOT * CH];
__device__ float g_vn   [BSZ * TTOT * CH];
__device__ float g_q    [BSZ * TTOT * CH];
__device__ float g_cn   [BSZ * SCTX * CH];
__device__ float g_k    [BSZ * SCTX * CH];
__device__ float g_val  [BSZ * SCTX * CH];
__device__ float g_o    [BSZ * TTOT * CH];
__device__ float g_delta[BSZ * TTOT * CH];
__device__ float g_g1   [BSZ * TTOT * (CH / 2)];
__device__ float g_nv   [BSZ * TTOT * CH];
__device__ int   g_sidx [BSZ * SCTX];
__device__ int   g_scnt [BSZ];

__global__ void gather_kernel(const float* __restrict__ in, float* __restrict__ v,
                              int hw, int tstart)
{
    __shared__ float tile[32][33];
    int b = blockIdx.z, ch0 = blockIdx.y * 32, p0 = blockIdx.x * 32;
    int tx = threadIdx.x, ty = threadIdx.y;
#pragma unroll
    for (int i = 0; i < 4; i++) {
        int ch = ch0 + ty + i * 8, p = p0 + tx;
        if (p < hw) tile[ty + i * 8][tx] = in[((size_t)(b * CH + ch)) * hw + p];
    }
    __syncthreads();
#pragma unroll
    for (int i = 0; i < 4; i++) {
        int p = p0 + ty + i * 8, ch = ch0 + tx;
        if (p < hw) v[((size_t)(b * TTOT + tstart + p)) * CH + ch] = tile[tx][ty + i * 8];
    }
}

__global__ void scatter_kernel(const float* __restrict__ nv, float* __restrict__ out,
                               int hw, int tstart, size_t obase)
{
    __shared__ float tile[32][33];
    int b = blockIdx.z, ch0 = blockIdx.y * 32, p0 = blockIdx.x * 32;
    int tx = threadIdx.x, ty = threadIdx.y;
#pragma unroll
    for (int i = 0; i < 4; i++) {
        int p = p0 + ty + i * 8, ch = ch0 + tx;
        if (p < hw) tile[ty + i * 8][tx] = nv[((size_t)(b * TTOT + tstart + p)) * CH + ch];
    }
    __syncthreads();
#pragma unroll
    for (int i = 0; i < 4; i++) {
        int ch = ch0 + ty + i * 8, p = p0 + tx;
        if (p < hw) out[obase + ((size_t)(b * CH + ch)) * hw + p] = tile[tx][ty + i * 8];
    }
}

__global__ void ln_kernel(const float* __restrict__ x, const float* __restrict__ gg,
                          const float* __restrict__ bb, float* __restrict__ y)
{
    int row = blockIdx.x, tid = threadIdx.x;
    float v = x[(size_t)row * CH + tid];
    float s = v, sq = v * v;
#pragma unroll
    for (int o = 16; o > 0; o >>= 1) {
        s  += __shfl_xor_sync(0xffffffffu, s,  o);
        sq += __shfl_xor_sync(0xffffffffu, sq, o);
    }
    __shared__ float ss[8], ssq[8];
    int w = tid >> 5, l = tid & 31;
    if (l == 0) { ss[w] = s; ssq[w] = sq; }
    __syncthreads();
    if (w == 0) {
        float s2 = ss[l & 7], q2 = ssq[l & 7];
#pragma unroll
        for (int o = 4; o > 0; o >>= 1) {
            s2 += __shfl_xor_sync(0xffffffffu, s2, o);
            q2 += __shfl_xor_sync(0xffffffffu, q2, o);
        }
        if (l == 0) { ss[0] = s2; ssq[0] = q2; }
    }
    __syncthreads();
    float mean = ss[0] * (1.0f / CH);
    float var  = ssq[0] * (1.0f / CH) - mean * mean;
    y[(size_t)row * CH + tid] = (v - mean) * rsqrtf(var + 1e-5f) * gg[tid] + bb[tid];
}

__global__ void compact_kernel(const int* __restrict__ mask, int* __restrict__ sidx,
                               int* __restrict__ scnt)
{
    int b = blockIdx.x, t = threadIdx.x;
    __shared__ int wsum[32];
    int m = mask[b * SCTX + t];
    unsigned bal = __ballot_sync(0xffffffffu, m != 0);
    int lane = t & 31, w = t >> 5;
    if (lane == 0) wsum[w] = __popc(bal);
    __syncthreads();
    if (w == 0) {
        int v = wsum[lane];
#pragma unroll
        for (int o = 1; o < 32; o <<= 1) {
            int n = __shfl_up_sync(0xffffffffu, v, o);
            if (lane >= o) v += n;
        }
        wsum[lane] = v;
    }
    __syncthreads();
    int base = (w == 0) ? 0 : wsum[w - 1];
    int pre  = __popc(bal & ((1u << lane) - 1u));
    if (m) sidx[b * SCTX + base + pre] = t;
    if (t == 0) scnt[b] = wsum[31];
}

// ---------------- GEMM: 128x128 block, 8x8/thread, swizzled B, FFMA2 ---------
#define GBM 128
#define GBN 128
#define GBK 32
#define BSW 144

template <int EPI>
__global__ void __launch_bounds__(256)
gemm_kernel(const float* __restrict__ A, const float* __restrict__ W,
            const float* __restrict__ bias, float* __restrict__ Cm,
            int M, int N, int K, float scale,
            const float* __restrict__ vres, const float* __restrict__ dres)
{
    __shared__ __align__(16) float Ast[GBK * 132];
    __shared__ __align__(16) float Bs [GBK * BSW];
    int bm = blockIdx.y * GBM, bn = blockIdx.x * GBN, tid = threadIdx.x;
    int trow = tid >> 4, tcol = tid & 15;
    ull acc2[4][8] = {};
    for (int k0 = 0; k0 < K; k0 += GBK) {
#pragma unroll
        for (int e = 0; e < 4; e++) {
            int lin = tid + e * 256;
            int r = lin >> 3, c4 = (lin & 7) << 2, gr = bm + r;
            float4 av = make_float4(0.f, 0.f, 0.f, 0.f);
            if (gr < M) av = *(const float4*)&A[(size_t)gr * K + k0 + c4];
            Ast[(c4 + 0) * 132 + r] = av.x;
            Ast[(c4 + 1) * 132 + r] = av.y;
            Ast[(c4 + 2) * 132 + r] = av.z;
            Ast[(c4 + 3) * 132 + r] = av.w;
        }
#pragma unroll
        for (int e = 0; e < 4; e++) {
            int lin = tid + e * 256;
            int r = lin >> 5, c4 = (lin & 31) << 2;
            float4 wv = *(const float4*)&W[(size_t)(k0 + r) * N + bn + c4];
            float* bp = &Bs[r * BSW + c4 + (c4 >> 3)];
            bp[0] = wv.x; bp[1] = wv.y; bp[2] = wv.z; bp[3] = wv.w;
        }
        __syncthreads();
#pragma unroll
        for (int k = 0; k < GBK; k++) {
            ulonglong2 aL = *(const ulonglong2*)&Ast[k * 132 + trow * 8];
            ulonglong2 aH = *(const ulonglong2*)&Ast[k * 132 + trow * 8 + 4];
            const float* br = &Bs[k * BSW + tcol * 9];
            ull a4[4] = {aL.x, aL.y, aH.x, aH.y};
#pragma unroll
            for (int j = 0; j < 8; j++) {
                ull bb = bcast2(br[j]);
                fma2(acc2[0][j], a4[0], bb);
                fma2(acc2[1][j], a4[1], bb);
                fma2(acc2[2][j], a4[2], bb);
                fma2(acc2[3][j], a4[3], bb);
            }
        }
        __syncthreads();
    }
    float bb8[8];
    *(float4*)&bb8[0] = *(const float4*)&bias[bn + tcol * 8];
    *(float4*)&bb8[4] = *(const float4*)&bias[bn + tcol * 8 + 4];
#pragma unroll
    for (int rp = 0; rp < 4; rp++) {
        float lo[8], hi[8];
#pragma unroll
        for (int j = 0; j < 8; j++) {
            float2 c = unpack2(acc2[rp][j]);
            lo[j] = c.x + bb8[j]; hi[j] = c.y + bb8[j];
        }
#pragma unroll
        for (int hh = 0; hh < 2; hh++) {
            int gr = bm + trow * 8 + rp * 2 + hh;
            if (gr >= M) continue;
            float* vv = hh ? hi : lo;
#pragma unroll
            for (int j = 0; j < 8; j++) {
                float val = vv[j];
                if (EPI == 1) val *= scale;
                if (EPI == 2) val = fmaxf(val, 0.0f);
                if (EPI == 3) {
                    size_t ridx = (size_t)gr * 256 + bn + tcol * 8 + j;
                    val = vres[ridx] + tanhf(val) * dres[ridx];
                }
                vv[j] = val;
            }
            *(float4*)&Cm[(size_t)gr * N + bn + tcol * 8] =
                make_float4(vv[0], vv[1], vv[2], vv[3]);
            *(float4*)&Cm[(size_t)gr * N + bn + tcol * 8 + 4] =
                make_float4(vv[4], vv[5], vv[6], vv[7]);
        }
    }
}

// ---------------- flash attention: AQ=AS=128, fused softmax, 4-way PV --------
#define AQ 128
#define AS 128
#define QS 0
#define KS 4224
#define VSO 8832
#define LSO 13440
#define RM 30400
#define RL 30528
#define RF 30656
#define ATTN_SMEM_BYTES (30784 * 4)

__device__ __forceinline__ int soff(int s) { return s * 132 + ((s >> 3) << 2); }

__global__ void __launch_bounds__(256)
attn_kernel(const float* __restrict__ Qb, const float* __restrict__ Kb,
            const float* __restrict__ Vb, const int* __restrict__ sidxp,
            const int* __restrict__ scnt, float* __restrict__ Ob)
{
    extern __shared__ __align__(16) float sm[];
    int b = blockIdx.z, h = blockIdx.y, t0 = blockIdx.x * AQ, tid = threadIdx.x;
    int trow = tid >> 4, tcol = tid & 15;
    int part = tid >> 6, rowg = (tid >> 2) & 15, dimg = tid & 3;
    int cnt = scnt[b];

    if (tid < AQ) { sm[RM + tid] = -INFINITY; sm[RL + tid] = 0.0f; }

#pragma unroll
    for (int e = 0; e < 4; e++) {
        int lin = tid + e * 256;
        int r = lin >> 3, c4 = (lin & 7) << 2, t = t0 + r;
        float4 qv = make_float4(0.f, 0.f, 0.f, 0.f);
        if (t < TTOT) qv = *(const float4*)&Qb[((size_t)(b * TTOT + t)) * CH + h * HD + c4];
        sm[QS + (c4 + 0) * 132 + r] = qv.x;
        sm[QS + (c4 + 1) * 132 + r] = qv.y;
        sm[QS + (c4 + 2) * 132 + r] = qv.z;
        sm[QS + (c4 + 3) * 132 + r] = qv.w;
    }

    ull acc2[4][8] = {};

    for (int s0 = 0; s0 < cnt; s0 += AS) {
        int rem = cnt - s0;
        __syncthreads();
        // K (col-swizzled transposed) / V (d-swizzled row-major) fill
#pragma unroll
        for (int e = 0; e < 4; e++) {
            int lin = tid + e * 256;
            int sr = lin >> 3, c4 = (lin & 7) << 2;
            int sidx = (sr < rem) ? sidxp[b * SCTX + s0 + sr] : 0;
            size_t gbase = ((size_t)(b * SCTX + sidx)) * CH + h * HD + c4;
            float4 kv = *(const float4*)&Kb[gbase];
            float4 vv = *(const float4*)&Vb[gbase];
            int sc = sr + (sr >> 3);
            sm[KS + (c4 + 0) * 144 + sc] = kv.x;
            sm[KS + (c4 + 1) * 144 + sc] = kv.y;
            sm[KS + (c4 + 2) * 144 + sc] = kv.z;
            sm[KS + (c4 + 3) * 144 + sc] = kv.w;
            float* vq = &sm[VSO + sr * 36 + c4 + (c4 >> 3)];
            vq[0] = vv.x; vq[1] = vv.y; vq[2] = vv.z; vq[3] = vv.w;
        }
        __syncthreads();

        // QK 8x8 micro-tile
        ull lg2[4][8] = {};
#pragma unroll
        for (int k = 0; k < HD; k++) {
            ulonglong2 aL = *(const ulonglong2*)&sm[QS + k * 132 + trow * 8];
            ulonglong2 aH = *(const ulonglong2*)&sm[QS + k * 132 + trow * 8 + 4];
            const float* br = &sm[KS + k * 144 + tcol * 9];
            ull a4[4] = {aL.x, aL.y, aH.x, aH.y};
#pragma unroll
            for (int j = 0; j < 8; j++) {
                ull bb = bcast2(br[j]);
                fma2(lg2[0][j], a4[0], bb);
                fma2(lg2[1][j], a4[1], bb);
                fma2(lg2[2][j], a4[2], bb);
                fma2(lg2[3][j], a4[3], bb);
            }
        }
        // clip + mask into p[8 rows][8 cols]
        float p[8][8];
#pragma unroll
        for (int j = 0; j < 8; j++) {
            float mj = (s0 + tcol * 8 + j < cnt) ? 1.0f : -9e15f;
#pragma unroll
            for (int rp = 0; rp < 4; rp++) {
                float2 c = unpack2(lg2[rp][j]);
                p[rp * 2 + 0][j] = fminf(fmaxf(c.x, -50000.0f), 50000.0f) + mj;
                p[rp * 2 + 1][j] = fminf(fmaxf(c.y, -50000.0f), 50000.0f) + mj;
            }
        }
        // fused online softmax: reduce over 16 tcol lanes (same half-warp)
        float rmax[8], csum[8], mold[8], newm[8];
#pragma unroll
        for (int i = 0; i < 8; i++) {
            float m0 = p[i][0];
#pragma unroll
            for (int j = 1; j < 8; j++) m0 = fmaxf(m0, p[i][j]);
            rmax[i] = m0;
        }
#pragma unroll
        for (int o = 1; o < 16; o <<= 1)
#pragma unroll
            for (int i = 0; i < 8; i++)
                rmax[i] = fmaxf(rmax[i], __shfl_xor_sync(0xffffffffu, rmax[i], o));
#pragma unroll
        for (int i = 0; i < 8; i++) {
            mold[i] = sm[RM + trow * 8 + i];
            newm[i] = fmaxf(mold[i], rmax[i]);
            float cs = 0.0f;
#pragma unroll
            for (int j = 0; j < 8; j++) {
                p[i][j] = __expf(p[i][j] - newm[i]);
                cs += p[i][j];
            }
            csum[i] = cs;
        }
#pragma unroll
        for (int o = 1; o < 16; o <<= 1)
#pragma unroll
            for (int i = 0; i < 8; i++)
                csum[i] += __shfl_xor_sync(0xffffffffu, csum[i], o);
        // store probs transposed+padded: [soff(s)][row]
#pragma unroll
        for (int j = 0; j < 8; j++) {
            int base = LSO + soff(tcol * 8 + j) + trow * 8;
            ulonglong2 v1, v2;
            v1.x = pack2(p[0][j], p[1][j]); v1.y = pack2(p[2][j], p[3][j]);
            v2.x = pack2(p[4][j], p[5][j]); v2.y = pack2(p[6][j], p[7][j]);
            *(ulonglong2*)&sm[base]     = v1;
            *(ulonglong2*)&sm[base + 4] = v2;
        }
        if (tcol == 0) {
#pragma unroll
            for (int i = 0; i < 8; i++) {
                int r = trow * 8 + i;
                float fc = __expf(mold[i] - newm[i]);
                sm[RF + r] = fc;
                sm[RL + r] = sm[RL + r] * fc + csum[i];
                sm[RM + r] = newm[i];
            }
        }
        __syncthreads();

        // PV: 4 s-partitions x (16 rowg x 4 dimg), 8 rows x 8 dims per thread
#pragma unroll
        for (int rp = 0; rp < 4; rp++) {
            ull fp = *(const ull*)&sm[RF + rowg * 8 + rp * 2];
#pragma unroll
            for (int j = 0; j < 8; j++) mul2(acc2[rp][j], fp);
        }
        int sbeg = part * 32;
#pragma unroll 4
        for (int ss = 0; ss < 32; ss++) {
            int s = sbeg + ss;
            ulonglong2 pL = *(const ulonglong2*)&sm[LSO + soff(s) + rowg * 8];
            ulonglong2 pH = *(const ulonglong2*)&sm[LSO + soff(s) + rowg * 8 + 4];
            const float* vr = &sm[VSO + s * 36 + dimg * 9];
            ull a4[4] = {pL.x, pL.y, pH.x, pH.y};
#pragma unroll
            for (int j = 0; j < 8; j++) {
                ull vb = bcast2(vr[j]);
                fma2(acc2[0][j], a4[0], vb);
                fma2(acc2[1][j], a4[1], vb);
                fma2(acc2[2][j], a4[2], vb);
                fma2(acc2[3][j], a4[3], vb);
            }
        }
    }

    __syncthreads();
    // merge partitions 1..3 via smem (reuses Q/K/V space)
    if (part > 0) {
        float* mb = &sm[(part - 1) * 4096];
#pragma unroll
        for (int rp = 0; rp < 4; rp++)
#pragma unroll
            for (int j = 0; j < 8; j++) {
                float2 c = unpack2(acc2[rp][j]);
                int row = rowg * 8 + rp * 2;
                mb[(row + 0) * 32 + dimg * 8 + j] = c.x;
                mb[(row + 1) * 32 + dimg * 8 + j] = c.y;
            }
    }
    __syncthreads();
    if (part == 0) {
#pragma unroll
        for (int rp = 0; rp < 4; rp++) {
#pragma unroll
            for (int hh = 0; hh < 2; hh++) {
                int row = rowg * 8 + rp * 2 + hh;
                int t = t0 + row;
                if (t >= TTOT) continue;
                float inv = 1.0f / sm[RL + row];
                float o8[8];
#pragma unroll
                for (int j = 0; j < 8; j++) {
                    float2 c = unpack2(acc2[rp][j]);
                    float v = hh ? c.y : c.x;
                    v += sm[0 * 4096 + row * 32 + dimg * 8 + j];
                    v += sm[1 * 4096 + row * 32 + dimg * 8 + j];
                    v += sm[2 * 4096 + row * 32 + dimg * 8 + j];
                    o8[j] = v * inv;
                }
                float* ob = &Ob[((size_t)(b * TTOT + t)) * CH + h * HD + dimg * 8];
                *(float4*)&ob[0] = make_float4(o8[0], o8[1], o8[2], o8[3]);
                *(float4*)&ob[4] = make_float4(o8[4], o8[5], o8[6], o8[7]);
            }
        }
    }
}

// ---------------- launch ------------------------------------------------------
extern "C" void kernel_launch(void* const* d_in, const int* in_sizes, int n_in,
                              void* d_out, int out_size)
{
    const float* qin[5];
    for (int i = 0; i < 5; i++) qin[i] = (const float*)d_in[i];
    const float* cache  = (const float*)d_in[5];
    const int*   mask   = (const int*)d_in[6];
    const float* ln_v_g = (const float*)d_in[7];
    const float* ln_v_b = (const float*)d_in[8];
    const float* ln_c_g = (const float*)d_in[9];
    const float* ln_c_b = (const float*)d_in[10];
    const float* Wv  = (const float*)d_in[11];
    const float* bv  = (const float*)d_in[12];
    const float* Wc  = (const float*)d_in[13];
    const float* bc  = (const float*)d_in[14];
    const float* Wvc = (const float*)d_in[15];
    const float* bvc = (const float*)d_in[16];
    const float* Wo  = (const float*)d_in[17];
    const float* bo  = (const float*)d_in[18];
    const float* Wg1 = (const float*)d_in[19];
    const float* bg1 = (const float*)d_in[20];
    const float* Wg2 = (const float*)d_in[21];
    const float* bg2 = (const float*)d_in[22];
    float* out = (float*)d_out;

    float *pv, *pvn, *pq, *pcn, *pk, *pval, *po, *pdelta, *pg1, *pnv;
    int *psidx, *pscnt;
    cudaGetSymbolAddress((void**)&pv,     g_v);
    cudaGetSymbolAddress((void**)&pvn,    g_vn);
    cudaGetSymbolAddress((void**)&pq,     g_q);
    cudaGetSymbolAddress((void**)&pcn,    g_cn);
    cudaGetSymbolAddress((void**)&pk,     g_k);
    cudaGetSymbolAddress((void**)&pval,   g_val);
    cudaGetSymbolAddress((void**)&po,     g_o);
    cudaGetSymbolAddress((void**)&pdelta, g_delta);
    cudaGetSymbolAddress((void**)&pg1,    g_g1);
    cudaGetSymbolAddress((void**)&pnv,    g_nv);
    cudaGetSymbolAddress((void**)&psidx,  g_sidx);
    cudaGetSymbolAddress((void**)&pscnt,  g_scnt);

    cudaFuncSetAttribute(attn_kernel,
                         cudaFuncAttributeMaxDynamicSharedMemorySize, ATTN_SMEM_BYTES);

    static const int    hw[5] = {6400, 1600, 400, 100, 25};
    static const int    st[5] = {0, 6400, 8000, 8400, 8500};
    static const size_t ob[5] = {0, 3276800, 4096000, 4300800, 4352000};

    const int MROWS = BSZ * TTOT;               // 17050
    const int CROWS = BSZ * SCTX;               // 2048
    const float scale = 0.1767766952966369f;    // 32^-0.5

    dim3 tb(32, 8);
    for (int lv = 0; lv < 5; lv++) {
        dim3 grid((hw[lv] + 31) / 32, CH / 32, BSZ);
        gather_kernel<<<grid, tb>>>(qin[lv], pv, hw[lv], st[lv]);
    }

    compact_kernel<<<BSZ, 1024>>>(mask, psidx, pscnt);

    ln_kernel<<<MROWS, 256>>>(pv, ln_v_g, ln_v_b, pvn);
    ln_kernel<<<CROWS, 256>>>(cache, ln_c_g, ln_c_b, pcn);

    dim3 gq(CH / GBN, (MROWS + GBM - 1) / GBM);   // (2, 134)
    dim3 gc(CH / GBN, CROWS / GBM);               // (2, 16)
    gemm_kernel<1><<<gq, 256>>>(pvn, Wv, bv, pq, MROWS, CH, CH, scale, nullptr, nullptr);
    gemm_kernel<0><<<gc, 256>>>(pcn, Wc,  bc,  pk,   CROWS, CH, CH, 1.0f, nullptr, nullptr);
    gemm_kernel<0><<<gc, 256>>>(pcn, Wvc, bvc, pval, CROWS, CH, CH, 1.0f, nullptr, nullptr);

    dim3 ga((TTOT + AQ - 1) / AQ, NH, BSZ);       // (67, 8, 2)
    attn_kernel<<<ga, 256, ATTN_SMEM_BYTES>>>(pq, pk, pval, psidx, pscnt, po);

    gemm_kernel<0><<<gq, 256>>>(po, Wo, bo, pdelta, MROWS, CH, CH, 1.0f, nullptr, nullptr);

    dim3 gg1(1, (MROWS + GBM - 1) / GBM);         // N = 128
    gemm_kernel<2><<<gg1, 256>>>(pv, Wg1, bg1, pg1, MROWS, CH / 2, CH, 1.0f, nullptr, nullptr);

    gemm_kernel<3><<<gq, 256>>>(pg1, Wg2, bg2, pnv, MROWS, CH, CH / 2, 1.0f, pv, pdelta);

    for (int lv = 0; lv < 5; lv++) {
        dim3 grid((hw[lv] + 31) / 32, CH / 32, BSZ);
        scatter_kernel<<<grid, tb>>>(pnv, out, hw[lv], st[lv], ob[lv]);
    }
}

// round 13
// speedup vs baseline: 1.1107x; 1.1107x over previous
#include <cuda_runtime.h>
#include <math.h>

#define BSZ   2
#define CH    256
#define SCTX  1024
#define NH    8
#define HD    32
#define TTOT  8525

typedef unsigned long long ull;

__device__ __forceinline__ void fma2(ull& d, ull a, ull b) {
    asm("fma.rn.f32x2 %0, %1, %2, %0;" : "+l"(d) : "l"(a), "l"(b));
}
__device__ __forceinline__ void mul2(ull& d, ull a) {
    asm("mul.rn.f32x2 %0, %0, %1;" : "+l"(d) : "l"(a));
}
__device__ __forceinline__ ull bcast2(float f) {
    ull d; unsigned u = __float_as_uint(f);
    asm("mov.b64 %0, {%1, %1};" : "=l"(d) : "r"(u));
    return d;
}
__device__ __forceinline__ ull pack2(float lo, float hi) {
    ull d; unsigned a = __float_as_uint(lo), b = __float_as_uint(hi);
    asm("mov.b64 %0, {%1, %2};" : "=l"(d) : "r"(a), "r"(b));
    return d;
}
__device__ __forceinline__ float2 unpack2(ull v) {
    unsigned lo, hi;
    asm("mov.b64 {%0, %1}, %2;" : "=r"(lo), "=r"(hi) : "l"(v));
    return make_float2(__uint_as_float(lo), __uint_as_float(hi));
}

__device__ float g_v    [BSZ * TTOT * CH];
__device__ float g_vn   [BSZ * TTOT * CH];
__device__ float g_q    [BSZ * TTOT * CH];
__device__ float g_cn   [BSZ * SCTX * CH];
__device__ float g_k    [BSZ * SCTX * CH];
__device__ float g_val  [BSZ * SCTX * CH];
__device__ float g_o    [BSZ * TTOT * CH];
__device__ float g_delta[BSZ * TTOT * CH];
__device__ float g_g1   [BSZ * TTOT * (CH / 2)];
__device__ float g_nv   [BSZ * TTOT * CH];
__device__ int   g_sidx [BSZ * SCTX];
__device__ int   g_scnt [BSZ];

// ---------------- merged gather: all 5 levels, p-tiles 200/50/13/4/1 ---------
__global__ void gather_all_kernel(const float* __restrict__ q0, const float* __restrict__ q1,
                                  const float* __restrict__ q2, const float* __restrict__ q3,
                                  const float* __restrict__ q4, float* __restrict__ v)
{
    __shared__ float tile[32][33];
    int bx = blockIdx.x;
    const float* in; int hw, tstart, p0;
    if      (bx < 200) { in = q0; hw = 6400; tstart = 0;    p0 = bx * 32; }
    else if (bx < 250) { in = q1; hw = 1600; tstart = 6400; p0 = (bx - 200) * 32; }
    else if (bx < 263) { in = q2; hw = 400;  tstart = 8000; p0 = (bx - 250) * 32; }
    else if (bx < 267) { in = q3; hw = 100;  tstart = 8400; p0 = (bx - 263) * 32; }
    else               { in = q4; hw = 25;   tstart = 8500; p0 = (bx - 267) * 32; }
    int b = blockIdx.z, ch0 = blockIdx.y * 32;
    int tx = threadIdx.x, ty = threadIdx.y;
#pragma unroll
    for (int i = 0; i < 4; i++) {
        int ch = ch0 + ty + i * 8, p = p0 + tx;
        if (p < hw) tile[ty + i * 8][tx] = in[((size_t)(b * CH + ch)) * hw + p];
    }
    __syncthreads();
#pragma unroll
    for (int i = 0; i < 4; i++) {
        int p = p0 + ty + i * 8, ch = ch0 + tx;
        if (p < hw) v[((size_t)(b * TTOT + tstart + p)) * CH + ch] = tile[tx][ty + i * 8];
    }
}

// ---------------- merged scatter ---------------------------------------------
__global__ void scatter_all_kernel(const float* __restrict__ nv, float* __restrict__ out)
{
    __shared__ float tile[32][33];
    int bx = blockIdx.x;
    int hw, tstart, p0; size_t obase;
    if      (bx < 200) { hw = 6400; tstart = 0;    obase = 0;       p0 = bx * 32; }
    else if (bx < 250) { hw = 1600; tstart = 6400; obase = 3276800; p0 = (bx - 200) * 32; }
    else if (bx < 263) { hw = 400;  tstart = 8000; obase = 4096000; p0 = (bx - 250) * 32; }
    else if (bx < 267) { hw = 100;  tstart = 8400; obase = 4300800; p0 = (bx - 263) * 32; }
    else               { hw = 25;   tstart = 8500; obase = 4352000; p0 = (bx - 267) * 32; }
    int b = blockIdx.z, ch0 = blockIdx.y * 32;
    int tx = threadIdx.x, ty = threadIdx.y;
#pragma unroll
    for (int i = 0; i < 4; i++) {
        int p = p0 + ty + i * 8, ch = ch0 + tx;
        if (p < hw) tile[ty + i * 8][tx] = nv[((size_t)(b * TTOT + tstart + p)) * CH + ch];
    }
    __syncthreads();
#pragma unroll
    for (int i = 0; i < 4; i++) {
        int ch = ch0 + ty + i * 8, p = p0 + tx;
        if (p < hw) out[obase + ((size_t)(b * CH + ch)) * hw + p] = tile[tx][ty + i * 8];
    }
}

__global__ void ln_kernel(const float* __restrict__ x, const float* __restrict__ gg,
                          const float* __restrict__ bb, float* __restrict__ y)
{
    int row = blockIdx.x, tid = threadIdx.x;
    float v = x[(size_t)row * CH + tid];
    float s = v, sq = v * v;
#pragma unroll
    for (int o = 16; o > 0; o >>= 1) {
        s  += __shfl_xor_sync(0xffffffffu, s,  o);
        sq += __shfl_xor_sync(0xffffffffu, sq, o);
    }
    __shared__ float ss[8], ssq[8];
    int w = tid >> 5, l = tid & 31;
    if (l == 0) { ss[w] = s; ssq[w] = sq; }
    __syncthreads();
    if (w == 0) {
        float s2 = ss[l & 7], q2 = ssq[l & 7];
#pragma unroll
        for (int o = 4; o > 0; o >>= 1) {
            s2 += __shfl_xor_sync(0xffffffffu, s2, o);
            q2 += __shfl_xor_sync(0xffffffffu, q2, o);
        }
        if (l == 0) { ss[0] = s2; ssq[0] = q2; }
    }
    __syncthreads();
    float mean = ss[0] * (1.0f / CH);
    float var  = ssq[0] * (1.0f / CH) - mean * mean;
    y[(size_t)row * CH + tid] = (v - mean) * rsqrtf(var + 1e-5f) * gg[tid] + bb[tid];
}

__global__ void compact_kernel(const int* __restrict__ mask, int* __restrict__ sidx,
                               int* __restrict__ scnt)
{
    int b = blockIdx.x, t = threadIdx.x;
    __shared__ int wsum[32];
    int m = mask[b * SCTX + t];
    unsigned bal = __ballot_sync(0xffffffffu, m != 0);
    int lane = t & 31, w = t >> 5;
    if (lane == 0) wsum[w] = __popc(bal);
    __syncthreads();
    if (w == 0) {
        int v = wsum[lane];
#pragma unroll
        for (int o = 1; o < 32; o <<= 1) {
            int n = __shfl_up_sync(0xffffffffu, v, o);
            if (lane >= o) v += n;
        }
        wsum[lane] = v;
    }
    __syncthreads();
    int base = (w == 0) ? 0 : wsum[w - 1];
    int pre  = __popc(bal & ((1u << lane) - 1u));
    if (m) sidx[b * SCTX + base + pre] = t;
    if (t == 0) scnt[b] = wsum[31];
}

// ---------------- GEMM: 128x128 block, 8x8/thread, swizzled B, FFMA2 ---------
#define GBM 128
#define GBN 128
#define GBK 32
#define BSW 144

template <int EPI>
__global__ void __launch_bounds__(256)
gemm_kernel(const float* __restrict__ A, const float* __restrict__ W,
            const float* __restrict__ bias, float* __restrict__ Cm,
            int M, int N, int K, float scale,
            const float* __restrict__ vres, const float* __restrict__ dres)
{
    __shared__ __align__(16) float Ast[GBK * 132];
    __shared__ __align__(16) float Bs [GBK * BSW];
    int bm = blockIdx.y * GBM, bn = blockIdx.x * GBN, tid = threadIdx.x;
    int trow = tid >> 4, tcol = tid & 15;
    ull acc2[4][8] = {};
    for (int k0 = 0; k0 < K; k0 += GBK) {
#pragma unroll
        for (int e = 0; e < 4; e++) {
            int lin = tid + e * 256;
            int r = lin >> 3, c4 = (lin & 7) << 2, gr = bm + r;
            float4 av = make_float4(0.f, 0.f, 0.f, 0.f);
            if (gr < M) av = *(const float4*)&A[(size_t)gr * K + k0 + c4];
            Ast[(c4 + 0) * 132 + r] = av.x;
            Ast[(c4 + 1) * 132 + r] = av.y;
            Ast[(c4 + 2) * 132 + r] = av.z;
            Ast[(c4 + 3) * 132 + r] = av.w;
        }
#pragma unroll
        for (int e = 0; e < 4; e++) {
            int lin = tid + e * 256;
            int r = lin >> 5, c4 = (lin & 31) << 2;
            float4 wv = *(const float4*)&W[(size_t)(k0 + r) * N + bn + c4];
            float* bp = &Bs[r * BSW + c4 + (c4 >> 3)];
            bp[0] = wv.x; bp[1] = wv.y; bp[2] = wv.z; bp[3] = wv.w;
        }
        __syncthreads();
#pragma unroll
        for (int k = 0; k < GBK; k++) {
            ulonglong2 aL = *(const ulonglong2*)&Ast[k * 132 + trow * 8];
            ulonglong2 aH = *(const ulonglong2*)&Ast[k * 132 + trow * 8 + 4];
            const float* br = &Bs[k * BSW + tcol * 9];
            ull a4[4] = {aL.x, aL.y, aH.x, aH.y};
#pragma unroll
            for (int j = 0; j < 8; j++) {
                ull bb = bcast2(br[j]);
                fma2(acc2[0][j], a4[0], bb);
                fma2(acc2[1][j], a4[1], bb);
                fma2(acc2[2][j], a4[2], bb);
                fma2(acc2[3][j], a4[3], bb);
            }
        }
        __syncthreads();
    }
    float bb8[8];
    *(float4*)&bb8[0] = *(const float4*)&bias[bn + tcol * 8];
    *(float4*)&bb8[4] = *(const float4*)&bias[bn + tcol * 8 + 4];
#pragma unroll
    for (int rp = 0; rp < 4; rp++) {
        float lo[8], hi[8];
#pragma unroll
        for (int j = 0; j < 8; j++) {
            float2 c = unpack2(acc2[rp][j]);
            lo[j] = c.x + bb8[j]; hi[j] = c.y + bb8[j];
        }
#pragma unroll
        for (int hh = 0; hh < 2; hh++) {
            int gr = bm + trow * 8 + rp * 2 + hh;
            if (gr >= M) continue;
            float* vv = hh ? hi : lo;
#pragma unroll
            for (int j = 0; j < 8; j++) {
                float val = vv[j];
                if (EPI == 1) val *= scale;
                if (EPI == 2) val = fmaxf(val, 0.0f);
                if (EPI == 3) {
                    size_t ridx = (size_t)gr * 256 + bn + tcol * 8 + j;
                    val = vres[ridx] + tanhf(val) * dres[ridx];
                }
                vv[j] = val;
            }
            *(float4*)&Cm[(size_t)gr * N + bn + tcol * 8] =
                make_float4(vv[0], vv[1], vv[2], vv[3]);
            *(float4*)&Cm[(size_t)gr * N + bn + tcol * 8 + 4] =
                make_float4(vv[4], vv[5], vv[6], vv[7]);
        }
    }
}

// ---------------- flash attention (proven R4 config): AQ=128, AS=64 ----------
#define AQ 128
#define AS 64
#define ATTN_SMEM_FLOATS 17536
#define ATTN_SMEM_BYTES  (ATTN_SMEM_FLOATS * 4)

__global__ void __launch_bounds__(256)
attn_kernel(const float* __restrict__ Qb, const float* __restrict__ Kb,
            const float* __restrict__ Vb, const int* __restrict__ sidxp,
            const int* __restrict__ scnt, float* __restrict__ Ob)
{
    extern __shared__ __align__(16) float sm[];
    float* Qst    = sm;            // [k][row] stride 132
    float* Kst    = sm + 4224;     // [k][s]   stride 68
    float* Vs     = sm + 6400;     // [s][d]   stride 36
    float* Lst    = sm + 8704;     // [s][row] stride 132
    float* rowm   = sm + 17152;
    float* rowl   = sm + 17280;
    float* rowfac = sm + 17408;

    int b = blockIdx.z, h = blockIdx.y, t0 = blockIdx.x * AQ, tid = threadIdx.x;
    int trow = tid >> 4, tcol = tid & 15;
    int cnt = scnt[b];

    if (tid < AQ) { rowm[tid] = -INFINITY; rowl[tid] = 0.0f; }

#pragma unroll
    for (int e = 0; e < 4; e++) {
        int lin = tid + e * 256;
        int r = lin >> 3, c4 = (lin & 7) << 2, t = t0 + r;
        float4 qv = make_float4(0.f, 0.f, 0.f, 0.f);
        if (t < TTOT) qv = *(const float4*)&Qb[((size_t)(b * TTOT + t)) * CH + h * HD + c4];
        Qst[(c4 + 0) * 132 + r] = qv.x;
        Qst[(c4 + 1) * 132 + r] = qv.y;
        Qst[(c4 + 2) * 132 + r] = qv.z;
        Qst[(c4 + 3) * 132 + r] = qv.w;
    }

    ull acc2[4][2] = {};

    for (int s0 = 0; s0 < cnt; s0 += AS) {
        int rem = cnt - s0;
        __syncthreads();
#pragma unroll
        for (int e = 0; e < 2; e++) {
            int lin = tid + e * 256;
            int sr = lin >> 3, c4 = (lin & 7) << 2;
            int sidx = (sr < rem) ? sidxp[b * SCTX + s0 + sr] : 0;
            size_t gbase = ((size_t)(b * SCTX + sidx)) * CH + h * HD + c4;
            float4 kv = *(const float4*)&Kb[gbase];
            float4 vv = *(const float4*)&Vb[gbase];
            Kst[(c4 + 0) * 68 + sr] = kv.x;
            Kst[(c4 + 1) * 68 + sr] = kv.y;
            Kst[(c4 + 2) * 68 + sr] = kv.z;
            Kst[(c4 + 3) * 68 + sr] = kv.w;
            *(float4*)&Vs[sr * 36 + c4] = vv;
        }
        __syncthreads();

        ull lg2[4][4] = {};
#pragma unroll
        for (int k = 0; k < HD; k++) {
            ulonglong2 aL = *(const ulonglong2*)&Qst[k * 132 + trow * 8];
            ulonglong2 aH = *(const ulonglong2*)&Qst[k * 132 + trow * 8 + 4];
            float4 kv = *(const float4*)&Kst[k * 68 + tcol * 4];
            ull b0 = bcast2(kv.x), b1 = bcast2(kv.y);
            ull b2 = bcast2(kv.z), b3 = bcast2(kv.w);
            fma2(lg2[0][0], aL.x, b0); fma2(lg2[0][1], aL.x, b1);
            fma2(lg2[0][2], aL.x, b2); fma2(lg2[0][3], aL.x, b3);
            fma2(lg2[1][0], aL.y, b0); fma2(lg2[1][1], aL.y, b1);
            fma2(lg2[1][2], aL.y, b2); fma2(lg2[1][3], aL.y, b3);
            fma2(lg2[2][0], aH.x, b0); fma2(lg2[2][1], aH.x, b1);
            fma2(lg2[2][2], aH.x, b2); fma2(lg2[2][3], aH.x, b3);
            fma2(lg2[3][0], aH.y, b0); fma2(lg2[3][1], aH.y, b1);
            fma2(lg2[3][2], aH.y, b2); fma2(lg2[3][3], aH.y, b3);
        }
#pragma unroll
        for (int j = 0; j < 4; j++) {
            float mj = (s0 + tcol * 4 + j < cnt) ? 1.0f : -9e15f;
            ulonglong2 stL, stH;
            {
                float2 c = unpack2(lg2[0][j]);
                c.x = fminf(fmaxf(c.x, -50000.0f), 50000.0f) + mj;
                c.y = fminf(fmaxf(c.y, -50000.0f), 50000.0f) + mj;
                stL.x = pack2(c.x, c.y);
            }
            {
                float2 c = unpack2(lg2[1][j]);
                c.x = fminf(fmaxf(c.x, -50000.0f), 50000.0f) + mj;
                c.y = fminf(fmaxf(c.y, -50000.0f), 50000.0f) + mj;
                stL.y = pack2(c.x, c.y);
            }
            {
                float2 c = unpack2(lg2[2][j]);
                c.x = fminf(fmaxf(c.x, -50000.0f), 50000.0f) + mj;
                c.y = fminf(fmaxf(c.y, -50000.0f), 50000.0f) + mj;
                stH.x = pack2(c.x, c.y);
            }
            {
                float2 c = unpack2(lg2[3][j]);
                c.x = fminf(fmaxf(c.x, -50000.0f), 50000.0f) + mj;
                c.y = fminf(fmaxf(c.y, -50000.0f), 50000.0f) + mj;
                stH.y = pack2(c.x, c.y);
            }
            int sIdx = tcol * 4 + j;
            *(ulonglong2*)&Lst[sIdx * 132 + trow * 8]     = stL;
            *(ulonglong2*)&Lst[sIdx * 132 + trow * 8 + 4] = stH;
        }
        __syncthreads();

        {
            int r = tid >> 1, half = tid & 1;
            float v[32];
#pragma unroll
            for (int q = 0; q < 32; q++)
                v[q] = Lst[(half * 32 + q) * 132 + r];
            float mold = rowm[r];
            float cmax = -INFINITY;
#pragma unroll
            for (int j = 0; j < 32; j++) cmax = fmaxf(cmax, v[j]);
            cmax = fmaxf(cmax, __shfl_xor_sync(0xffffffffu, cmax, 1));
            float newm = fmaxf(mold, cmax);
            float csum = 0.0f;
#pragma unroll
            for (int j = 0; j < 32; j++) {
                v[j] = __expf(v[j] - newm);
                csum += v[j];
            }
#pragma unroll
            for (int q = 0; q < 32; q++)
                Lst[(half * 32 + q) * 132 + r] = v[q];
            csum += __shfl_xor_sync(0xffffffffu, csum, 1);
            float fac = __expf(mold - newm);
            if (half == 0) {
                rowfac[r] = fac;
                rowl[r]   = rowl[r] * fac + csum;
                rowm[r]   = newm;
            }
        }
        __syncthreads();

        {
#pragma unroll
            for (int rp = 0; rp < 4; rp++) {
                ull fpair = *(const ull*)&rowfac[trow * 8 + rp * 2];
                mul2(acc2[rp][0], fpair);
                mul2(acc2[rp][1], fpair);
            }
#pragma unroll 8
            for (int s = 0; s < AS; s++) {
                ulonglong2 pL = *(const ulonglong2*)&Lst[s * 132 + trow * 8];
                ulonglong2 pH = *(const ulonglong2*)&Lst[s * 132 + trow * 8 + 4];
                float2 v2 = *(const float2*)&Vs[s * 36 + tcol * 2];
                ull vb0 = bcast2(v2.x), vb1 = bcast2(v2.y);
                fma2(acc2[0][0], pL.x, vb0); fma2(acc2[0][1], pL.x, vb1);
                fma2(acc2[1][0], pL.y, vb0); fma2(acc2[1][1], pL.y, vb1);
                fma2(acc2[2][0], pH.x, vb0); fma2(acc2[2][1], pH.x, vb1);
                fma2(acc2[3][0], pH.y, vb0); fma2(acc2[3][1], pH.y, vb1);
            }
        }
    }

#pragma unroll
    for (int rp = 0; rp < 4; rp++) {
        float2 d0 = unpack2(acc2[rp][0]);
        float2 d1 = unpack2(acc2[rp][1]);
        int rowA = trow * 8 + rp * 2;
        int tA = t0 + rowA, tB = tA + 1;
        if (tA < TTOT) {
            float inv = 1.0f / rowl[rowA];
            *(float2*)&Ob[((size_t)(b * TTOT + tA)) * CH + h * HD + tcol * 2] =
                make_float2(d0.x * inv, d1.x * inv);
        }
        if (tB < TTOT) {
            float inv = 1.0f / rowl[rowA + 1];
            *(float2*)&Ob[((size_t)(b * TTOT + tB)) * CH + h * HD + tcol * 2] =
                make_float2(d0.y * inv, d1.y * inv);
        }
    }
}

// ---------------- launch ------------------------------------------------------
extern "C" void kernel_launch(void* const* d_in, const int* in_sizes, int n_in,
                              void* d_out, int out_size)
{
    const float* qin[5];
    for (int i = 0; i < 5; i++) qin[i] = (const float*)d_in[i];
    const float* cache  = (const float*)d_in[5];
    const int*   mask   = (const int*)d_in[6];
    const float* ln_v_g = (const float*)d_in[7];
    const float* ln_v_b = (const float*)d_in[8];
    const float* ln_c_g = (const float*)d_in[9];
    const float* ln_c_b = (const float*)d_in[10];
    const float* Wv  = (const float*)d_in[11];
    const float* bv  = (const float*)d_in[12];
    const float* Wc  = (const float*)d_in[13];
    const float* bc  = (const float*)d_in[14];
    const float* Wvc = (const float*)d_in[15];
    const float* bvc = (const float*)d_in[16];
    const float* Wo  = (const float*)d_in[17];
    const float* bo  = (const float*)d_in[18];
    const float* Wg1 = (const float*)d_in[19];
    const float* bg1 = (const float*)d_in[20];
    const float* Wg2 = (const float*)d_in[21];
    const float* bg2 = (const float*)d_in[22];
    float* out = (float*)d_out;

    float *pv, *pvn, *pq, *pcn, *pk, *pval, *po, *pdelta, *pg1, *pnv;
    int *psidx, *pscnt;
    cudaGetSymbolAddress((void**)&pv,     g_v);
    cudaGetSymbolAddress((void**)&pvn,    g_vn);
    cudaGetSymbolAddress((void**)&pq,     g_q);
    cudaGetSymbolAddress((void**)&pcn,    g_cn);
    cudaGetSymbolAddress((void**)&pk,     g_k);
    cudaGetSymbolAddress((void**)&pval,   g_val);
    cudaGetSymbolAddress((void**)&po,     g_o);
    cudaGetSymbolAddress((void**)&pdelta, g_delta);
    cudaGetSymbolAddress((void**)&pg1,    g_g1);
    cudaGetSymbolAddress((void**)&pnv,    g_nv);
    cudaGetSymbolAddress((void**)&psidx,  g_sidx);
    cudaGetSymbolAddress((void**)&pscnt,  g_scnt);

    cudaFuncSetAttribute(attn_kernel,
                         cudaFuncAttributeMaxDynamicSharedMemorySize, ATTN_SMEM_BYTES);

    const int MROWS = BSZ * TTOT;               // 17050
    const int CROWS = BSZ * SCTX;               // 2048
    const float scale = 0.1767766952966369f;    // 32^-0.5

    dim3 tb(32, 8);
    dim3 gg(268, CH / 32, BSZ);                 // 268 p-tiles across 5 levels

    // launch order chosen so ncu -s 5 -c 1 lands on the big Wv GEMM (idx 5)
    gather_all_kernel<<<gg, tb>>>(qin[0], qin[1], qin[2], qin[3], qin[4], pv); // 0
    compact_kernel<<<BSZ, 1024>>>(mask, psidx, pscnt);                          // 1
    ln_kernel<<<MROWS, 256>>>(pv, ln_v_g, ln_v_b, pvn);                         // 2
    ln_kernel<<<CROWS, 256>>>(cache, ln_c_g, ln_c_b, pcn);                      // 3

    dim3 gq(CH / GBN, (MROWS + GBM - 1) / GBM);   // (2, 134)
    dim3 gc(CH / GBN, CROWS / GBM);               // (2, 16)
    gemm_kernel<0><<<gc, 256>>>(pcn, Wc,  bc,  pk,   CROWS, CH, CH, 1.0f, nullptr, nullptr); // 4
    gemm_kernel<1><<<gq, 256>>>(pvn, Wv, bv, pq, MROWS, CH, CH, scale, nullptr, nullptr);    // 5 <- profiled
    gemm_kernel<0><<<gc, 256>>>(pcn, Wvc, bvc, pval, CROWS, CH, CH, 1.0f, nullptr, nullptr); // 6

    dim3 ga((TTOT + AQ - 1) / AQ, NH, BSZ);       // (67, 8, 2)
    attn_kernel<<<ga, 256, ATTN_SMEM_BYTES>>>(pq, pk, pval, psidx, pscnt, po);  // 7

    gemm_kernel<0><<<gq, 256>>>(po, Wo, bo, pdelta, MROWS, CH, CH, 1.0f, nullptr, nullptr);  // 8

    dim3 gg1(1, (MROWS + GBM - 1) / GBM);         // N = 128
    gemm_kernel<2><<<gg1, 256>>>(pv, Wg1, bg1, pg1, MROWS, CH / 2, CH, 1.0f, nullptr, nullptr); // 9
    gemm_kernel<3><<<gq, 256>>>(pg1, Wg2, bg2, pnv, MROWS, CH, CH / 2, 1.0f, pv, pdelta);       // 10

    scatter_all_kernel<<<gg, tb>>>(pnv, out);                                   // 11
}